// round 13
// baseline (speedup 1.0000x reference)
#include <cuda_runtime.h>
#include <cuda_bf16.h>
#include <cuda_fp16.h>
#include <math.h>
#include <stdint.h>

typedef unsigned long long u64;

#define BB   8
#define LL   1024
#define HHN  8
#define NQV  4
#define BHN  (BB*HHN)
#define CTX_ELEMS (BB*LL*HHN*64)
#define PI_F 3.14159274101257324f

// Q: Karatsuba bf16-split, SCALED by 128: [bh][pos][96 bf16]
__device__ __nv_bfloat16 g_qA[(size_t)BHN * 1024 * 96];
// K interleaved: [bh][s][24 u64], u64_j = hi_u32(j) | lo_u32(j)<<32
__device__ u64 g_kBi[(size_t)BHN * 1024 * 24];
// V fp16: [bh][spair 0..511][d 0..63] u32 = f16x2(v[2s,d], v[2s+1,d])
__device__ uint32_t g_vH[(size_t)BHN * 512 * 64];

// ---------------- helpers ----------------
__device__ __forceinline__ void mma_bf16(float4& c, const uint32_t a[4],
                                         uint32_t b0, uint32_t b1) {
    asm("mma.sync.aligned.m16n8k16.row.col.f32.bf16.bf16.f32 "
        "{%0,%1,%2,%3},{%4,%5,%6,%7},{%8,%9},{%0,%1,%2,%3};"
        : "+f"(c.x), "+f"(c.y), "+f"(c.z), "+f"(c.w)
        : "r"(a[0]), "r"(a[1]), "r"(a[2]), "r"(a[3]), "r"(b0), "r"(b1));
}
__device__ __forceinline__ void mma_f16(float4& c, const uint32_t a[4],
                                        uint32_t b0, uint32_t b1) {
    asm("mma.sync.aligned.m16n8k16.row.col.f32.f16.f16.f32 "
        "{%0,%1,%2,%3},{%4,%5,%6,%7},{%8,%9},{%0,%1,%2,%3};"
        : "+f"(c.x), "+f"(c.y), "+f"(c.z), "+f"(c.w)
        : "r"(a[0]), "r"(a[1]), "r"(a[2]), "r"(a[3]), "r"(b0), "r"(b1));
}
__device__ __forceinline__ uint32_t bfpack(float a, float b) {   // a->low
    uint32_t r; asm("cvt.rn.bf16x2.f32 %0, %1, %2;" : "=r"(r) : "f"(b), "f"(a)); return r;
}
__device__ __forceinline__ uint32_t hfpack(float a, float b) {   // a->low
    uint32_t r; asm("cvt.rn.f16x2.f32 %0, %1, %2;" : "=r"(r) : "f"(b), "f"(a)); return r;
}
__device__ __forceinline__ float bflowf(uint32_t v)  { return __uint_as_float(v << 16); }
__device__ __forceinline__ float bfhighf(uint32_t v) { return __uint_as_float(v & 0xFFFF0000u); }
__device__ __forceinline__ void cpa16s(uint32_t saddr, const void* gsrc) {
    asm volatile("cp.async.cg.shared.global [%0], [%1], 16;" :: "r"(saddr), "l"(gsrc));
}
__device__ __forceinline__ void cpa_commit() {
    asm volatile("cp.async.commit_group;" ::: "memory");
}
template<int N>
__device__ __forceinline__ void cpa_wait() {
    asm volatile("cp.async.wait_group %0;" :: "n"(N) : "memory");
}
__device__ __forceinline__ uint32_t s2u(const void* p) {
    return (uint32_t)__cvta_generic_to_shared(p);
}

// ======================================================================
// Prep: Q encode (0..255, scaled x128), K encode (256..511), V fp16 (512..767)
// ======================================================================
#define PREP_SMEM (128 * 264 * 2)
__global__ void __launch_bounds__(256) prep_kernel(
    const float* __restrict__ qin, const float* __restrict__ kin,
    const float* __restrict__ vin,
    const float* __restrict__ wq, const float* __restrict__ bq,
    const float* __restrict__ wk, const float* __restrict__ bk)
{
    extern __shared__ __half smH[];
    __shared__ float sw[NQV * 64];
    __shared__ float sb[NQV];
    const int bid = blockIdx.x;
    const int tid = threadIdx.x;

    if (bid >= 512) {   // ---- V fp16 transpose + pair pack ----
        int vb = bid - 512;
        int bh = vb >> 2, sc0 = (vb & 3) * 256;
        int b = bh >> 3, h = bh & 7;
        const float4* vg = (const float4*)vin;
#pragma unroll
        for (int j = 0; j < 16; j++) {
            int i = tid + j * 256;
            int s = i >> 4, d4 = i & 15;
            float4 xv = vg[((size_t)((b * 1024 + sc0 + s) * 8 + h)) * 16 + d4];
            const float* px = &xv.x;
#pragma unroll
            for (int jj = 0; jj < 4; jj++)
                smH[(d4 * 4 + jj) * 264 + s] = __float2half_rn(px[jj]);
        }
        __syncthreads();
        uint32_t* dst = g_vH + (size_t)bh * 32768;
#pragma unroll
        for (int j = 0; j < 8; j++) {
            int i = tid + j * 256;            // 0..2047
            int sp = i >> 4;                  // local spair 0..127
            int dq = (i & 15) * 4;            // d quad
            uint32_t vals[4];
#pragma unroll
            for (int k = 0; k < 4; k++) {
                uint32_t lo = __half_as_ushort(smH[(dq + k) * 264 + 2 * sp]);
                uint32_t hi = __half_as_ushort(smH[(dq + k) * 264 + 2 * sp + 1]);
                vals[k] = lo | (hi << 16);
            }
            *(uint4*)&dst[((size_t)(sc0 >> 1) + sp) * 64 + dq] =
                make_uint4(vals[0], vals[1], vals[2], vals[3]);
        }
        return;
    }

    const int isK = (bid >= 256);
    const float* x = isK ? kin : qin;
    const float* w = isK ? wk : wq;
    const float* bias = isK ? bk : bq;
    if (tid < NQV * 64) sw[tid] = w[tid];
    if (tid < NQV) sb[tid] = bias[tid];
    __syncthreads();

    int n  = (bid & 255) * 256 + tid;
    int bh = n >> 10, loc = n & 1023;
    int b = bh >> 3, h = bh & 7;
    const float* xr = x + (size_t)((b * 1024 + loc) * HHN + h) * 64;

    float th[NQV];
#pragma unroll
    for (int j = 0; j < NQV; j++) th[j] = sb[j];
#pragma unroll 4
    for (int d = 0; d < 64; d += 4) {
        float4 xv = *(const float4*)(xr + d);
#pragma unroll
        for (int j = 0; j < NQV; j++) {
            th[j] += xv.x * sw[j * 64 + d]     + xv.y * sw[j * 64 + d + 1]
                   + xv.z * sw[j * 64 + d + 2] + xv.w * sw[j * 64 + d + 3];
        }
    }
#pragma unroll
    for (int j = 0; j < NQV; j++) th[j] = tanhf(th[j]) * PI_F;
    float bt[3];
#pragma unroll
    for (int p = 0; p < 3; p++) bt[p] = th[p] * th[p + 1];

    float co[16], si[16];
#pragma unroll
    for (int d = 0; d < 16; d++) {
        float a = 0.f;
        a += ((d >> 3) & 1) ? -th[0] : th[0];
        a += ((d >> 2) & 1) ? -th[1] : th[1];
        a += ((d >> 1) & 1) ? -th[2] : th[2];
        a += ( d       & 1) ? -th[3] : th[3];
        a += (((d >> 3) ^ (d >> 2)) & 1) ? -bt[0] : bt[0];
        a += (((d >> 2) ^ (d >> 1)) & 1) ? -bt[1] : bt[1];
        a += (((d >> 1) ^  d      ) & 1) ? -bt[2] : bt[2];
        sincosf(-0.5f * a, &si[d], &co[d]);
    }
    float re[16], im[16];
#pragma unroll
    for (int d = 0; d < 16; d++) { re[d] = co[d]; im[d] = si[d]; }
#pragma unroll
    for (int hs = 1; hs < 16; hs <<= 1) {
#pragma unroll
        for (int i = 0; i < 16; i++) {
            if ((i & hs) == 0) {
                int j2 = i | hs;
                float ar = re[i], ai = im[i], br = re[j2], bi = im[j2];
                re[i] = ar + br;  im[i] = ai + bi;
                re[j2] = ar - br; im[j2] = ai - bi;
            }
        }
    }

    // Q gets scale 128 (0.0625*128 = 8) so p' = (128*fid)^2 = 2^14 * p
    const float sc = isK ? 0.0625f : 8.0f;
    float fr[16], fi[16], fs[16];
#pragma unroll
    for (int d = 0; d < 16; d++) {
        float tr = re[d] * sc, ti = im[d] * sc;
        fr[d] = tr * co[d] - ti * si[d];
        fi[d] = tr * si[d] + ti * co[d];
        fs[d] = isK ? (fr[d] - fi[d]) : (fr[d] + fi[d]);
    }

    uint32_t uw[48];
#pragma unroll
    for (int j = 0; j < 8; j++) {
        uint32_t hp;
        hp = bfpack(fr[2*j], fr[2*j+1]);
        uw[j] = hp;
        uw[24 + j] = bfpack(fr[2*j] - bflowf(hp), fr[2*j+1] - bfhighf(hp));
        hp = bfpack(fi[2*j], fi[2*j+1]);
        uw[8 + j] = hp;
        uw[32 + j] = bfpack(fi[2*j] - bflowf(hp), fi[2*j+1] - bfhighf(hp));
        hp = bfpack(fs[2*j], fs[2*j+1]);
        uw[16 + j] = hp;
        uw[40 + j] = bfpack(fs[2*j] - bflowf(hp), fs[2*j+1] - bfhighf(hp));
    }
    if (!isK) {
        uint4* o4 = (uint4*)(g_qA + (size_t)n * 96);
#pragma unroll
        for (int q = 0; q < 12; q++)
            o4[q] = make_uint4(uw[4*q], uw[4*q+1], uw[4*q+2], uw[4*q+3]);
    } else {
        ulonglong2* o2 = (ulonglong2*)(g_kBi + (size_t)n * 24);
#pragma unroll
        for (int j = 0; j < 12; j++)
            o2[j] = make_ulonglong2((u64)uw[2*j]   | ((u64)uw[24 + 2*j]   << 32),
                                    (u64)uw[2*j+1] | ((u64)uw[24 + 2*j+1] << 32));
    }
}

// ======================================================================
// Fused attention: fp16 scores (scaled 2^14), occ 3.
// smem: scores [16][524] u32 (33536 B) + 8 x 3584 B warp buffers = 62208 B
// ======================================================================
#define SC_STRIDE 524
#define SC_BYTES (16 * SC_STRIDE * 4)       // 33536
#define WBUF_BYTES 3584
#define KSTG 224                            // u64 per K stage (8 rows x 28)
#define VSTG 320                            // u32 per V stage (8 rows x 40)
#define SMEM_BYTES (SC_BYTES + 8 * WBUF_BYTES)   // 62208

__global__ void __launch_bounds__(256, 3) attn_fused(float* __restrict__ out)
{
    extern __shared__ uint32_t smb[];
    uint32_t* sc32 = smb;                    // [16][524] fp16x2 score pairs
    __shared__ float sred[8][16];
    __shared__ float sinv[16];

    const int bh = blockIdx.y;
    const int l0 = blockIdx.x * 16;
    const int b = bh >> 3, h = bh & 7;
    const int tid = threadIdx.x;
    const int w = tid >> 5, lane = tid & 31;
    const int gr = lane >> 2, ctg = lane & 3;

    char* wbufb = (char*)smb + SC_BYTES + w * WBUF_BYTES;
    u64* kbuf = (u64*)wbufb;
    uint32_t* vbuf = (uint32_t*)wbufb;
    const uint32_t wsa = s2u(wbufb);

    // resident bf16 Q fragments (scaled x128)
    uint32_t Ah[3][4], Al[3][4];
    {
        const uint32_t* qa = (const uint32_t*)g_qA + (size_t)bh * 49152 + (size_t)l0 * 48;
#pragma unroll
        for (int g = 0; g < 3; g++) {
            Ah[g][0] = qa[gr * 48 + g * 8 + ctg];
            Ah[g][1] = qa[(gr + 8) * 48 + g * 8 + ctg];
            Ah[g][2] = qa[gr * 48 + g * 8 + 4 + ctg];
            Ah[g][3] = qa[(gr + 8) * 48 + g * 8 + 4 + ctg];
            Al[g][0] = qa[gr * 48 + 24 + g * 8 + ctg];
            Al[g][1] = qa[(gr + 8) * 48 + 24 + g * 8 + ctg];
            Al[g][2] = qa[gr * 48 + 24 + g * 8 + 4 + ctg];
            Al[g][3] = qa[(gr + 8) * 48 + 24 + g * 8 + 4 + ctg];
        }
    }

    // ---- phase A: per-warp pipelined scores ----
    const u64* kg = g_kBi + (size_t)bh * 24576;
    const int r0 = lane / 12, f0 = lane - r0 * 12;
    const int r1 = (lane + 32) / 12, f1 = (lane + 32) - r1 * 12;
    const int r2 = (lane + 64) / 12, f2 = (lane + 64) - r2 * 12;
    const uint32_t kd0 = wsa + (uint32_t)(r0 * 28 + f0 * 2) * 8;
    const uint32_t kd1 = wsa + (uint32_t)(r1 * 28 + f1 * 2) * 8;
    const uint32_t kd2 = wsa + (uint32_t)(r2 * 28 + f2 * 2) * 8;
    const u64* ks0 = kg + (w * 8 + r0) * 24 + f0 * 2;
    const u64* ks1 = kg + (w * 8 + r1) * 24 + f1 * 2;
    const u64* ks2 = kg + (w * 8 + r2) * 24 + f2 * 2;

    auto issueK = [&](int c) {
        const uint32_t so = (c & 1) ? (uint32_t)(KSTG * 8) : 0u;
        const size_t go = (size_t)c * 1536;
        cpa16s(kd0 + so, ks0 + go);
        cpa16s(kd1 + so, ks1 + go);
        cpa16s(kd2 + so, ks2 + go);
        cpa_commit();
    };

    uint32_t* srow0 = sc32 + gr * SC_STRIDE + w * 4 + ctg;
    uint32_t* srow1 = srow0 + 8 * SC_STRIDE;
    const u64* bb0 = kbuf + gr * 28;

    float rs0 = 0.f, rs1 = 0.f;
    issueK(0);
    issueK(1);

#pragma unroll 1
    for (int c = 0; c < 16; c++) {
        if (c < 15) cpa_wait<1>(); else cpa_wait<0>();
        __syncwarp();
        const u64* bb = bb0 + ((c & 1) ? KSTG : 0);

        u64 B0[3], B1[3];
#pragma unroll
        for (int g = 0; g < 3; g++) {
            B0[g] = bb[g * 8 + ctg];
            B1[g] = bb[g * 8 + 4 + ctg];
        }
        __syncwarp();
        if (c < 14) issueK(c + 2);

        float4 acc[3];
#pragma unroll
        for (int g = 0; g < 3; g++) acc[g] = make_float4(0.f, 0.f, 0.f, 0.f);
#pragma unroll
        for (int g = 0; g < 3; g++) {
            uint32_t bh0 = (uint32_t)B0[g], bh1 = (uint32_t)B1[g];
            uint32_t bl0 = (uint32_t)(B0[g] >> 32), bl1 = (uint32_t)(B1[g] >> 32);
            mma_bf16(acc[g], Ah[g], bh0, bh1);
            mma_bf16(acc[g], Ah[g], bl0, bl1);
            mma_bf16(acc[g], Al[g], bh0, bh1);
        }

        float4 c1 = acc[0], c2 = acc[1], c3 = acc[2];
        float fr, fi, p0, p1, p2, p3;
        fr = c1.x + c2.x; fi = c3.x - c1.x + c2.x; p0 = fr * fr + fi * fi;
        fr = c1.y + c2.y; fi = c3.y - c1.y + c2.y; p1 = fr * fr + fi * fi;
        fr = c1.z + c2.z; fi = c3.z - c1.z + c2.z; p2 = fr * fr + fi * fi;
        fr = c1.w + c2.w; fi = c3.w - c1.w + c2.w; p3 = fr * fr + fi * fi;

        srow0[c * 32] = hfpack(p0, p1);
        srow1[c * 32] = hfpack(p2, p3);
        rs0 += p0 + p1; rs1 += p2 + p3;
    }

    // ---- rowsums ----
    rs0 += __shfl_xor_sync(0xFFFFFFFFu, rs0, 1);
    rs0 += __shfl_xor_sync(0xFFFFFFFFu, rs0, 2);
    rs1 += __shfl_xor_sync(0xFFFFFFFFu, rs1, 1);
    rs1 += __shfl_xor_sync(0xFFFFFFFFu, rs1, 2);
    if (ctg == 0) { sred[w][gr] = rs0; sred[w][gr + 8] = rs1; }
    __syncthreads();

    // ---- phase C mapping: warp = (dq d-half, sh s-quarter) ----
    const int dq = w >> 2, sh = w & 3;
    const uint32_t* vG = g_vH + (size_t)bh * 32768 + (size_t)(sh * 128) * 64 + dq * 32;
    uint32_t vd[2]; const uint32_t* vs[2];
#pragma unroll
    for (int t = 0; t < 2; t++) {
        int sp = lane >> 2, qd = (lane & 3) + 4 * t;   // spair, d-quad
        vd[t] = wsa + (uint32_t)(sp * 40 + qd * 4) * 4;
        vs[t] = vG + (size_t)sp * 64 + qd * 4;
    }
    auto issueV = [&](int c) {
        const uint32_t so = (c & 1) ? (uint32_t)(VSTG * 4) : 0u;
        const size_t go = (size_t)c * 512;   // 8 spairs * 64
        cpa16s(vd[0] + so, vs[0] + go);
        cpa16s(vd[1] + so, vs[1] + go);
        cpa_commit();
    };
    issueV(0);
    issueV(1);

    if (tid < 16) {
        float s = 0.f;
#pragma unroll
        for (int ww = 0; ww < 8; ww++) s += sred[ww][tid];
        sinv[tid] = 1.0f / (s + 0.016384f);   // = 2^14 * (sum/2^14 + 1e-6)
    }
    __syncthreads();

    // ---- phase B: single normalized weights pass ----
    {
        float4* wout = (float4*)(out + (size_t)CTX_ELEMS + ((size_t)bh * 1024 + l0) * 1024);
#pragma unroll 4
        for (int i = tid; i < 4096; i += 256) {
            int row = i >> 8, pq = i & 255;
            uint2 v = *(const uint2*)&sc32[row * SC_STRIDE + pq * 2];
            float2 f0 = __half22float2(*(const half2*)&v.x);
            float2 f1 = __half22float2(*(const half2*)&v.y);
            float iv = sinv[row];
            wout[(size_t)row * 256 + pq] =
                make_float4(f0.x * iv, f0.y * iv, f1.x * iv, f1.y * iv);
        }
    }

    // ---- phase C main loop: 16 chunks of 8 spairs, fp16 mma ----
    float4 cac[4];
#pragma unroll
    for (int nt = 0; nt < 4; nt++) cac[nt] = make_float4(0.f, 0.f, 0.f, 0.f);

    const uint32_t* sr0 = sc32 + gr * SC_STRIDE + sh * 128 + ctg;
    const uint32_t* sr1 = sr0 + 8 * SC_STRIDE;

#pragma unroll 1
    for (int c = 0; c < 16; c++) {
        if (c < 15) cpa_wait<1>(); else cpa_wait<0>();
        __syncwarp();
        const uint32_t* vb = vbuf + ((c & 1) ? VSTG : 0);

        uint32_t b0[4], b1[4];
#pragma unroll
        for (int nt = 0; nt < 4; nt++) {
            b0[nt] = vb[ctg * 40 + nt * 8 + gr];
            b1[nt] = vb[(ctg + 4) * 40 + nt * 8 + gr];
        }
        uint32_t aH[4];
        aH[0] = sr0[c * 8];
        aH[1] = sr1[c * 8];
        aH[2] = sr0[c * 8 + 4];
        aH[3] = sr1[c * 8 + 4];
        __syncwarp();
        if (c < 14) issueV(c + 2);

#pragma unroll
        for (int nt = 0; nt < 4; nt++)
            mma_f16(cac[nt], aH, b0[nt], b1[nt]);
    }

    // ---- 4-way cross-s-quarter reduction (reuse warp-buffer smem) ----
    __syncthreads();
    float* pf = (float*)((char*)smb + SC_BYTES);   // [8 warps][16 l][stride 40]
    {
        float* pw = pf + w * 640;
#pragma unroll
        for (int nt = 0; nt < 4; nt++) {
            *(float2*)(pw + gr * 40 + nt * 8 + 2 * ctg) = make_float2(cac[nt].x, cac[nt].y);
            *(float2*)(pw + (gr + 8) * 40 + nt * 8 + 2 * ctg) = make_float2(cac[nt].z, cac[nt].w);
        }
    }
    __syncthreads();
    {
        int l = tid >> 4, dqd = tid & 15;
        int wb = (dqd >= 8) ? 4 : 0;
        int col = (dqd & 7) * 4;
        float4 sum = make_float4(0.f, 0.f, 0.f, 0.f);
#pragma unroll
        for (int s = 0; s < 4; s++) {
            float4 v = *(const float4*)(pf + (wb + s) * 640 + l * 40 + col);
            sum.x += v.x; sum.y += v.y; sum.z += v.z; sum.w += v.w;
        }
        float iv = sinv[l];
        sum.x *= iv; sum.y *= iv; sum.z *= iv; sum.w *= iv;
        *(float4*)&out[((size_t)((b * 1024 + l0 + l) * 8 + h)) * 64 + dqd * 4] = sum;
    }
}

// ======================================================================
extern "C" void kernel_launch(void* const* d_in, const int* in_sizes, int n_in,
                              void* d_out, int out_size)
{
    (void)in_sizes; (void)n_in; (void)out_size;
    const float* q  = (const float*)d_in[0];
    const float* k  = (const float*)d_in[1];
    const float* v  = (const float*)d_in[2];
    const float* wq = (const float*)d_in[3];
    const float* bq = (const float*)d_in[4];
    const float* wk = (const float*)d_in[5];
    const float* bk = (const float*)d_in[6];
    float* out = (float*)d_out;

    cudaFuncSetAttribute(prep_kernel, cudaFuncAttributeMaxDynamicSharedMemorySize, PREP_SMEM);
    cudaFuncSetAttribute(attn_fused,  cudaFuncAttributeMaxDynamicSharedMemorySize, SMEM_BYTES);

    prep_kernel<<<768, 256, PREP_SMEM>>>(q, k, v, wq, bq, wk, bk);
    attn_fused<<<dim3(64, BHN), 256, SMEM_BYTES>>>(out);
}

// round 14
// speedup vs baseline: 1.0880x; 1.0880x over previous
#include <cuda_runtime.h>
#include <cuda_bf16.h>
#include <cuda_fp16.h>
#include <math.h>
#include <stdint.h>

typedef unsigned long long u64;

#define BB   8
#define LL   1024
#define HHN  8
#define NQV  4
#define BHN  (BB*HHN)
#define CTX_ELEMS (BB*LL*HHN*64)
#define PI_F 3.14159274101257324f

// Q bf16-split, scaled x128: [bh][pos][96 bf16] = [qr_h|qi_h|nqr_h|qr_l|qi_l|nqr_l]
__device__ __nv_bfloat16 g_qA[(size_t)BHN * 1024 * 96];
// K interleaved: [bh][s][16 u64]: u64_m = hi_u32(m) | lo_u32(m)<<32, m: r pairs 0..7, i pairs 8..15
__device__ u64 g_kBi[(size_t)BHN * 1024 * 16];
// V fp16 paired: [bh][chunk 0..127][j 0..3][d 0..63] u64 = f16x2(spair c*8+j) | f16x2(spair c*8+j+4)<<32
__device__ u64 g_vV[(size_t)BHN * 128 * 4 * 64];

// ---------------- helpers ----------------
__device__ __forceinline__ void mma_bf16(float4& c, const uint32_t a[4],
                                         uint32_t b0, uint32_t b1) {
    asm("mma.sync.aligned.m16n8k16.row.col.f32.bf16.bf16.f32 "
        "{%0,%1,%2,%3},{%4,%5,%6,%7},{%8,%9},{%0,%1,%2,%3};"
        : "+f"(c.x), "+f"(c.y), "+f"(c.z), "+f"(c.w)
        : "r"(a[0]), "r"(a[1]), "r"(a[2]), "r"(a[3]), "r"(b0), "r"(b1));
}
__device__ __forceinline__ void mma_f16(float4& c, const uint32_t a[4],
                                        uint32_t b0, uint32_t b1) {
    asm("mma.sync.aligned.m16n8k16.row.col.f32.f16.f16.f32 "
        "{%0,%1,%2,%3},{%4,%5,%6,%7},{%8,%9},{%0,%1,%2,%3};"
        : "+f"(c.x), "+f"(c.y), "+f"(c.z), "+f"(c.w)
        : "r"(a[0]), "r"(a[1]), "r"(a[2]), "r"(a[3]), "r"(b0), "r"(b1));
}
__device__ __forceinline__ uint32_t bfpack(float a, float b) {   // a->low
    uint32_t r; asm("cvt.rn.bf16x2.f32 %0, %1, %2;" : "=r"(r) : "f"(b), "f"(a)); return r;
}
__device__ __forceinline__ uint32_t hfpack(float a, float b) {   // a->low
    uint32_t r; asm("cvt.rn.f16x2.f32 %0, %1, %2;" : "=r"(r) : "f"(b), "f"(a)); return r;
}
__device__ __forceinline__ float bflowf(uint32_t v)  { return __uint_as_float(v << 16); }
__device__ __forceinline__ float bfhighf(uint32_t v) { return __uint_as_float(v & 0xFFFF0000u); }
__device__ __forceinline__ void cpa16s(uint32_t saddr, const void* gsrc) {
    asm volatile("cp.async.cg.shared.global [%0], [%1], 16;" :: "r"(saddr), "l"(gsrc));
}
__device__ __forceinline__ void cpa_commit() {
    asm volatile("cp.async.commit_group;" ::: "memory");
}
template<int N>
__device__ __forceinline__ void cpa_wait() {
    asm volatile("cp.async.wait_group %0;" :: "n"(N) : "memory");
}
__device__ __forceinline__ uint32_t s2u(const void* p) {
    return (uint32_t)__cvta_generic_to_shared(p);
}

// ======================================================================
// Prep: Q encode (0..255, x128, with -qr), K encode (256..511), V pack (512..767)
// ======================================================================
#define PREP_SMEM (64 * 264 * 2)
__global__ void __launch_bounds__(256) prep_kernel(
    const float* __restrict__ qin, const float* __restrict__ kin,
    const float* __restrict__ vin,
    const float* __restrict__ wq, const float* __restrict__ bq,
    const float* __restrict__ wk, const float* __restrict__ bk)
{
    extern __shared__ __half smH[];
    __shared__ float sw[NQV * 64];
    __shared__ float sb[NQV];
    const int bid = blockIdx.x;
    const int tid = threadIdx.x;

    if (bid >= 512) {   // ---- V fp16 transpose + spair-pair pack ----
        int vb = bid - 512;
        int bh = vb >> 2, sc0 = (vb & 3) * 256;
        int b = bh >> 3, h = bh & 7;
        const float4* vg = (const float4*)vin;
#pragma unroll
        for (int j = 0; j < 16; j++) {
            int i = tid + j * 256;
            int s = i >> 4, d4 = i & 15;
            float4 xv = vg[((size_t)((b * 1024 + sc0 + s) * 8 + h)) * 16 + d4];
            const float* px = &xv.x;
#pragma unroll
            for (int jj = 0; jj < 4; jj++)
                smH[(d4 * 4 + jj) * 264 + s] = __float2half_rn(px[jj]);
        }
        __syncthreads();
        u64* dst = g_vV + (size_t)bh * 32768;
#pragma unroll
        for (int j = 0; j < 8; j++) {
            int i = tid + j * 256;            // 0..2047
            int c = i >> 7;                   // local chunk 0..15
            int jj = (i >> 5) & 3;            // pair index
            int d0 = (i & 31) * 2;            // d, d+1
            int spA = c * 8 + jj, spB = spA + 4;   // local spairs
            u64 vv[2];
#pragma unroll
            for (int t = 0; t < 2; t++) {
                int d = d0 + t;
                uint32_t lo = (uint32_t)__half_as_ushort(smH[d * 264 + 2 * spA])
                            | ((uint32_t)__half_as_ushort(smH[d * 264 + 2 * spA + 1]) << 16);
                uint32_t hi = (uint32_t)__half_as_ushort(smH[d * 264 + 2 * spB])
                            | ((uint32_t)__half_as_ushort(smH[d * 264 + 2 * spB + 1]) << 16);
                vv[t] = (u64)lo | ((u64)hi << 32);
            }
            size_t base = ((size_t)((sc0 >> 4) + c) * 4 + jj) * 64 + d0;
            *(ulonglong2*)&dst[base] = make_ulonglong2(vv[0], vv[1]);
        }
        return;
    }

    const int isK = (bid >= 256);
    const float* x = isK ? kin : qin;
    const float* w = isK ? wk : wq;
    const float* bias = isK ? bk : bq;
    if (tid < NQV * 64) sw[tid] = w[tid];
    if (tid < NQV) sb[tid] = bias[tid];
    __syncthreads();

    int n  = (bid & 255) * 256 + tid;
    int bh = n >> 10, loc = n & 1023;
    int b = bh >> 3, h = bh & 7;
    const float* xr = x + (size_t)((b * 1024 + loc) * HHN + h) * 64;

    float th[NQV];
#pragma unroll
    for (int j = 0; j < NQV; j++) th[j] = sb[j];
#pragma unroll 4
    for (int d = 0; d < 64; d += 4) {
        float4 xv = *(const float4*)(xr + d);
#pragma unroll
        for (int j = 0; j < NQV; j++) {
            th[j] += xv.x * sw[j * 64 + d]     + xv.y * sw[j * 64 + d + 1]
                   + xv.z * sw[j * 64 + d + 2] + xv.w * sw[j * 64 + d + 3];
        }
    }
#pragma unroll
    for (int j = 0; j < NQV; j++) th[j] = tanhf(th[j]) * PI_F;
    float bt[3];
#pragma unroll
    for (int p = 0; p < 3; p++) bt[p] = th[p] * th[p + 1];

    float co[16], si[16];
#pragma unroll
    for (int d = 0; d < 16; d++) {
        float a = 0.f;
        a += ((d >> 3) & 1) ? -th[0] : th[0];
        a += ((d >> 2) & 1) ? -th[1] : th[1];
        a += ((d >> 1) & 1) ? -th[2] : th[2];
        a += ( d       & 1) ? -th[3] : th[3];
        a += (((d >> 3) ^ (d >> 2)) & 1) ? -bt[0] : bt[0];
        a += (((d >> 2) ^ (d >> 1)) & 1) ? -bt[1] : bt[1];
        a += (((d >> 1) ^  d      ) & 1) ? -bt[2] : bt[2];
        sincosf(-0.5f * a, &si[d], &co[d]);
    }
    float re[16], im[16];
#pragma unroll
    for (int d = 0; d < 16; d++) { re[d] = co[d]; im[d] = si[d]; }
#pragma unroll
    for (int hs = 1; hs < 16; hs <<= 1) {
#pragma unroll
        for (int i = 0; i < 16; i++) {
            if ((i & hs) == 0) {
                int j2 = i | hs;
                float ar = re[i], ai = im[i], br = re[j2], bi = im[j2];
                re[i] = ar + br;  im[i] = ai + bi;
                re[j2] = ar - br; im[j2] = ai - bi;
            }
        }
    }

    // Q scaled x128 (0.0625*128 = 8) -> p' = (128 fid)^2
    const float sc = isK ? 0.0625f : 8.0f;
    float fr[16], fi[16];
#pragma unroll
    for (int d = 0; d < 16; d++) {
        float tr = re[d] * sc, ti = im[d] * sc;
        fr[d] = tr * co[d] - ti * si[d];
        fi[d] = tr * si[d] + ti * co[d];
    }

    uint32_t uw[40];   // [qr_h 0..7][qi_h 8..15][qr_l 24..31][qi_l 32..39]
#pragma unroll
    for (int j = 0; j < 8; j++) {
        uint32_t hp;
        hp = bfpack(fr[2*j], fr[2*j+1]);
        uw[j] = hp;
        uw[24 + j] = bfpack(fr[2*j] - bflowf(hp), fr[2*j+1] - bfhighf(hp));
        hp = bfpack(fi[2*j], fi[2*j+1]);
        uw[8 + j] = hp;
        uw[32 + j] = bfpack(fi[2*j] - bflowf(hp), fi[2*j+1] - bfhighf(hp));
    }
    if (!isK) {
        // layout: [qr_h|qi_h|nqr_h|qr_l|qi_l|nqr_l] x 8 u32 each
        uint32_t o[48];
#pragma unroll
        for (int j = 0; j < 8; j++) {
            o[j]      = uw[j];
            o[8 + j]  = uw[8 + j];
            o[16 + j] = uw[j] ^ 0x80008000u;
            o[24 + j] = uw[24 + j];
            o[32 + j] = uw[32 + j];
            o[40 + j] = uw[24 + j] ^ 0x80008000u;
        }
        uint4* o4 = (uint4*)(g_qA + (size_t)n * 96);
#pragma unroll
        for (int q = 0; q < 12; q++)
            o4[q] = make_uint4(o[4*q], o[4*q+1], o[4*q+2], o[4*q+3]);
    } else {
        // u64_m = uw[m] | uw[24+m]<<32 for m 0..15
        ulonglong2* o2 = (ulonglong2*)(g_kBi + (size_t)n * 16);
#pragma unroll
        for (int j = 0; j < 8; j++)
            o2[j] = make_ulonglong2((u64)uw[2*j]   | ((u64)uw[24 + 2*j]   << 32),
                                    (u64)uw[2*j+1] | ((u64)uw[24 + 2*j+1] << 32));
    }
}

// ======================================================================
// Fused attention: direct 4-gemm scores (2 accumulators), fp16 context, occ 3.
// smem: scores 33536 B + 8 x 3840 B warp buffers = 64256 B
// ======================================================================
#define SC_STRIDE 524
#define SC_BYTES (16 * SC_STRIDE * 4)       // 33536
#define WBUF_BYTES 3840                      // 3 K stages (1280 each) / 2 V stages (1152)
#define SMEM_BYTES (SC_BYTES + 8 * WBUF_BYTES)   // 64256

__global__ void __launch_bounds__(256, 3) attn_fused(float* __restrict__ out)
{
    extern __shared__ uint32_t smb[];
    uint32_t* sc32 = smb;                    // [16][524] fp16x2 score pairs
    __shared__ float sred[8][16];
    __shared__ float sinv[16];

    const int bh = blockIdx.y;
    const int l0 = blockIdx.x * 16;
    const int b = bh >> 3, h = bh & 7;
    const int tid = threadIdx.x;
    const int w = tid >> 5, lane = tid & 31;
    const int gr = lane >> 2, ctg = lane & 3;

    char* wbufb = (char*)smb + SC_BYTES + w * WBUF_BYTES;
    const uint32_t wsa = s2u(wbufb);

    // resident bf16 Q fragments: g = {qr, qi, nqr}, hi+lo
    uint32_t Ah[3][4], Al[3][4];
    {
        const uint32_t* qa = (const uint32_t*)g_qA + (size_t)bh * 49152 + (size_t)l0 * 48;
#pragma unroll
        for (int g = 0; g < 3; g++) {
            Ah[g][0] = qa[gr * 48 + g * 8 + ctg];
            Ah[g][1] = qa[(gr + 8) * 48 + g * 8 + ctg];
            Ah[g][2] = qa[gr * 48 + g * 8 + 4 + ctg];
            Ah[g][3] = qa[(gr + 8) * 48 + g * 8 + 4 + ctg];
            Al[g][0] = qa[gr * 48 + 24 + g * 8 + ctg];
            Al[g][1] = qa[(gr + 8) * 48 + 24 + g * 8 + ctg];
            Al[g][2] = qa[gr * 48 + 24 + g * 8 + 4 + ctg];
            Al[g][3] = qa[(gr + 8) * 48 + 24 + g * 8 + 4 + ctg];
        }
    }

    // ---- phase A staging addresses ----
    const u64* kg = g_kBi + (size_t)bh * 16384;
    const int kr_ = lane >> 2, kq = lane & 3;
    const uint32_t kd0 = wsa + (uint32_t)(kr_ * 20 + kq * 2) * 8;
    const uint32_t kd1 = kd0 + 64;                      // +8 u64
    const u64* ks0 = kg + (w * 8 + kr_) * 16 + kq * 2;
    const u64* ks1 = ks0 + 8;

    auto issueK = [&](int c, uint32_t so) {
        const size_t go = (size_t)c * 1024;
        cpa16s(kd0 + so, ks0 + go);
        cpa16s(kd1 + so, ks1 + go);
        cpa_commit();
    };

    uint32_t* srow0 = sc32 + gr * SC_STRIDE + w * 4 + ctg;
    uint32_t* srow1 = srow0 + 8 * SC_STRIDE;

    float rs0 = 0.f, rs1 = 0.f;
    issueK(0, 0);
    issueK(1, 1280);
    issueK(2, 2560);
    uint32_t so = 0;

#pragma unroll 1
    for (int c = 0; c < 16; c++) {
        if (c < 14) cpa_wait<2>();
        else if (c == 14) cpa_wait<1>();
        else cpa_wait<0>();
        __syncwarp();
        const u64* bb = (const u64*)(wbufb + so) + gr * 20;

        u64 Br0 = bb[ctg];
        u64 Br1 = bb[4 + ctg];
        u64 Bi0 = bb[8 + ctg];
        u64 Bi1 = bb[12 + ctg];
        __syncwarp();
        if (c < 13) issueK(c + 3, so);
        so = (so == 2560) ? 0 : so + 1280;

        uint32_t krh0 = (uint32_t)Br0, krh1 = (uint32_t)Br1;
        uint32_t krl0 = (uint32_t)(Br0 >> 32), krl1 = (uint32_t)(Br1 >> 32);
        uint32_t kih0 = (uint32_t)Bi0, kih1 = (uint32_t)Bi1;
        uint32_t kil0 = (uint32_t)(Bi0 >> 32), kil1 = (uint32_t)(Bi1 >> 32);

        float4 fr4 = make_float4(0.f, 0.f, 0.f, 0.f);
        float4 fi4 = make_float4(0.f, 0.f, 0.f, 0.f);
        mma_bf16(fr4, Ah[0], krh0, krh1);
        mma_bf16(fi4, Ah[1], krh0, krh1);
        mma_bf16(fr4, Ah[0], krl0, krl1);
        mma_bf16(fi4, Ah[1], krl0, krl1);
        mma_bf16(fr4, Al[0], krh0, krh1);
        mma_bf16(fi4, Al[1], krh0, krh1);
        mma_bf16(fr4, Ah[1], kih0, kih1);
        mma_bf16(fi4, Ah[2], kih0, kih1);
        mma_bf16(fr4, Ah[1], kil0, kil1);
        mma_bf16(fi4, Ah[2], kil0, kil1);
        mma_bf16(fr4, Al[1], kih0, kih1);
        mma_bf16(fi4, Al[2], kih0, kih1);

        float p0 = fr4.x * fr4.x + fi4.x * fi4.x;
        float p1 = fr4.y * fr4.y + fi4.y * fi4.y;
        float p2 = fr4.z * fr4.z + fi4.z * fi4.z;
        float p3 = fr4.w * fr4.w + fi4.w * fi4.w;

        srow0[c * 32] = hfpack(p0, p1);
        srow1[c * 32] = hfpack(p2, p3);
        rs0 += p0 + p1; rs1 += p2 + p3;
    }

    // ---- rowsums ----
    rs0 += __shfl_xor_sync(0xFFFFFFFFu, rs0, 1);
    rs0 += __shfl_xor_sync(0xFFFFFFFFu, rs0, 2);
    rs1 += __shfl_xor_sync(0xFFFFFFFFu, rs1, 1);
    rs1 += __shfl_xor_sync(0xFFFFFFFFu, rs1, 2);
    if (ctg == 0) { sred[w][gr] = rs0; sred[w][gr + 8] = rs1; }
    __syncthreads();

    // ---- phase C mapping: warp = (dq d-half, sh s-quarter) ----
    const int dq = w >> 2, sh = w & 3;
    // chunks: global chunk index = sh*32 + c (c 0..31? no: 16 chunks of 8 spairs per quarter)
    const u64* vG = g_vV + (size_t)bh * 32768 + (size_t)(sh * 16) * 256 + dq * 32;
    const int vj = lane >> 3, vd8 = lane & 7;
    const uint32_t vdst0 = wsa + (uint32_t)(vj * 36 + vd8 * 2) * 8;
    const uint32_t vdst1 = vdst0 + 128;                 // +16 u64
    const u64* vsrc0 = vG + vj * 64 + vd8 * 2;
    const u64* vsrc1 = vsrc0 + 16;

    auto issueV = [&](int c) {
        const uint32_t vso = (c & 1) ? 1152u : 0u;
        const size_t go = (size_t)c * 256;
        cpa16s(vdst0 + vso, vsrc0 + go);
        cpa16s(vdst1 + vso, vsrc1 + go);
        cpa_commit();
    };
    issueV(0);
    issueV(1);

    if (tid < 16) {
        float s = 0.f;
#pragma unroll
        for (int ww = 0; ww < 8; ww++) s += sred[ww][tid];
        sinv[tid] = 1.0f / (s + 0.016384f);
    }
    __syncthreads();

    // ---- phase B: single normalized weights pass ----
    {
        float4* wout = (float4*)(out + (size_t)CTX_ELEMS + ((size_t)bh * 1024 + l0) * 1024);
#pragma unroll 4
        for (int i = tid; i < 4096; i += 256) {
            int row = i >> 8, pq = i & 255;
            uint2 v = *(const uint2*)&sc32[row * SC_STRIDE + pq * 2];
            float2 f0 = __half22float2(*(const half2*)&v.x);
            float2 f1 = __half22float2(*(const half2*)&v.y);
            float iv = sinv[row];
            wout[(size_t)row * 256 + pq] =
                make_float4(f0.x * iv, f0.y * iv, f1.x * iv, f1.y * iv);
        }
    }

    // ---- phase C main loop: 16 chunks of 8 spairs ----
    float4 cac[4];
#pragma unroll
    for (int nt = 0; nt < 4; nt++) cac[nt] = make_float4(0.f, 0.f, 0.f, 0.f);

    const uint32_t* sr0 = sc32 + gr * SC_STRIDE + sh * 128 + ctg;
    const uint32_t* sr1 = sr0 + 8 * SC_STRIDE;

#pragma unroll 1
    for (int c = 0; c < 16; c++) {
        if (c < 15) cpa_wait<1>(); else cpa_wait<0>();
        __syncwarp();
        const u64* vb = (const u64*)(wbufb + ((c & 1) ? 1152 : 0)) + ctg * 36;

        u64 bv[4];
#pragma unroll
        for (int nt = 0; nt < 4; nt++) bv[nt] = vb[nt * 8 + gr];
        uint32_t aH[4];
        aH[0] = sr0[c * 8];
        aH[1] = sr1[c * 8];
        aH[2] = sr0[c * 8 + 4];
        aH[3] = sr1[c * 8 + 4];
        __syncwarp();
        if (c < 14) issueV(c + 2);

#pragma unroll
        for (int nt = 0; nt < 4; nt++)
            mma_f16(cac[nt], aH, (uint32_t)bv[nt], (uint32_t)(bv[nt] >> 32));
    }

    // ---- 4-way cross-s-quarter reduction (reuse warp-buffer smem) ----
    __syncthreads();
    float* pf = (float*)((char*)smb + SC_BYTES);   // [8 warps][16 l][stride 40]
    {
        float* pw = pf + w * 640;
#pragma unroll
        for (int nt = 0; nt < 4; nt++) {
            *(float2*)(pw + gr * 40 + nt * 8 + 2 * ctg) = make_float2(cac[nt].x, cac[nt].y);
            *(float2*)(pw + (gr + 8) * 40 + nt * 8 + 2 * ctg) = make_float2(cac[nt].z, cac[nt].w);
        }
    }
    __syncthreads();
    {
        int l = tid >> 4, dqd = tid & 15;
        int wb = (dqd >= 8) ? 4 : 0;
        int col = (dqd & 7) * 4;
        float4 sum = make_float4(0.f, 0.f, 0.f, 0.f);
#pragma unroll
        for (int s = 0; s < 4; s++) {
            float4 v = *(const float4*)(pf + (wb + s) * 640 + l * 40 + col);
            sum.x += v.x; sum.y += v.y; sum.z += v.z; sum.w += v.w;
        }
        float iv = sinv[l];
        sum.x *= iv; sum.y *= iv; sum.z *= iv; sum.w *= iv;
        *(float4*)&out[((size_t)((b * 1024 + l0 + l) * 8 + h)) * 64 + dqd * 4] = sum;
    }
}

// ======================================================================
extern "C" void kernel_launch(void* const* d_in, const int* in_sizes, int n_in,
                              void* d_out, int out_size)
{
    (void)in_sizes; (void)n_in; (void)out_size;
    const float* q  = (const float*)d_in[0];
    const float* k  = (const float*)d_in[1];
    const float* v  = (const float*)d_in[2];
    const float* wq = (const float*)d_in[3];
    const float* bq = (const float*)d_in[4];
    const float* wk = (const float*)d_in[5];
    const float* bk = (const float*)d_in[6];
    float* out = (float*)d_out;

    cudaFuncSetAttribute(prep_kernel, cudaFuncAttributeMaxDynamicSharedMemorySize, PREP_SMEM);
    cudaFuncSetAttribute(attn_fused,  cudaFuncAttributeMaxDynamicSharedMemorySize, SMEM_BYTES);

    prep_kernel<<<768, 256, PREP_SMEM>>>(q, k, v, wq, bq, wk, bk);
    attn_fused<<<dim3(64, BHN), 256, SMEM_BYTES>>>(out);
}

// round 16
// speedup vs baseline: 1.1538x; 1.0605x over previous
#include <cuda_runtime.h>
#include <cuda_bf16.h>
#include <cuda_fp16.h>
#include <math.h>
#include <stdint.h>

typedef unsigned long long u64;

#define BB   8
#define LL   1024
#define HHN  8
#define NQV  4
#define BHN  (BB*HHN)
#define CTX_ELEMS (BB*LL*HHN*64)
#define PI_F 3.14159274101257324f

// Q bf16-split, scaled x128: [bh][pos][96 bf16] = [qr_h|qi_h|nqr_h|qr_l|qi_l|nqr_l]
__device__ __nv_bfloat16 g_qA[(size_t)BHN * 1024 * 96];
// K interleaved: [bh][s][16 u64]: u64_m = hi_u32(m) | lo_u32(m)<<32, m: r pairs 0..7, i pairs 8..15
__device__ u64 g_kBi[(size_t)BHN * 1024 * 16];
// V fp16 paired: [bh][chunk 0..127][j 0..3][d 0..63] u64 = f16x2(spair c*8+j) | f16x2(spair c*8+j+4)<<32
__device__ u64 g_vV[(size_t)BHN * 128 * 4 * 64];

// ---------------- helpers ----------------
__device__ __forceinline__ void mma_bf16(float4& c, const uint32_t a[4],
                                         uint32_t b0, uint32_t b1) {
    asm("mma.sync.aligned.m16n8k16.row.col.f32.bf16.bf16.f32 "
        "{%0,%1,%2,%3},{%4,%5,%6,%7},{%8,%9},{%0,%1,%2,%3};"
        : "+f"(c.x), "+f"(c.y), "+f"(c.z), "+f"(c.w)
        : "r"(a[0]), "r"(a[1]), "r"(a[2]), "r"(a[3]), "r"(b0), "r"(b1));
}
__device__ __forceinline__ void mma_f16(float4& c, const uint32_t a[4],
                                        uint32_t b0, uint32_t b1) {
    asm("mma.sync.aligned.m16n8k16.row.col.f32.f16.f16.f32 "
        "{%0,%1,%2,%3},{%4,%5,%6,%7},{%8,%9},{%0,%1,%2,%3};"
        : "+f"(c.x), "+f"(c.y), "+f"(c.z), "+f"(c.w)
        : "r"(a[0]), "r"(a[1]), "r"(a[2]), "r"(a[3]), "r"(b0), "r"(b1));
}
__device__ __forceinline__ uint32_t bfpack(float a, float b) {   // a->low
    uint32_t r; asm("cvt.rn.bf16x2.f32 %0, %1, %2;" : "=r"(r) : "f"(b), "f"(a)); return r;
}
__device__ __forceinline__ uint32_t hfpack(float a, float b) {   // a->low
    uint32_t r; asm("cvt.rn.f16x2.f32 %0, %1, %2;" : "=r"(r) : "f"(b), "f"(a)); return r;
}
__device__ __forceinline__ float bflowf(uint32_t v)  { return __uint_as_float(v << 16); }
__device__ __forceinline__ float bfhighf(uint32_t v) { return __uint_as_float(v & 0xFFFF0000u); }
__device__ __forceinline__ void cpa16s(uint32_t saddr, const void* gsrc) {
    asm volatile("cp.async.cg.shared.global [%0], [%1], 16;" :: "r"(saddr), "l"(gsrc));
}
__device__ __forceinline__ void cpa_commit() {
    asm volatile("cp.async.commit_group;" ::: "memory");
}
template<int N>
__device__ __forceinline__ void cpa_wait() {
    asm volatile("cp.async.wait_group %0;" :: "n"(N) : "memory");
}
__device__ __forceinline__ uint32_t s2u(const void* p) {
    return (uint32_t)__cvta_generic_to_shared(p);
}

// ======================================================================
// Prep: Q encode (0..255, x128, with -qr), K encode (256..511), V pack (512..767)
// ======================================================================
#define PREP_SMEM (64 * 264 * 2)
__global__ void __launch_bounds__(256) prep_kernel(
    const float* __restrict__ qin, const float* __restrict__ kin,
    const float* __restrict__ vin,
    const float* __restrict__ wq, const float* __restrict__ bq,
    const float* __restrict__ wk, const float* __restrict__ bk)
{
    extern __shared__ __half smH[];
    __shared__ float sw[NQV * 64];
    __shared__ float sb[NQV];
    const int bid = blockIdx.x;
    const int tid = threadIdx.x;

    if (bid >= 512) {   // ---- V fp16 transpose + spair-pair pack ----
        int vb = bid - 512;
        int bh = vb >> 2, sc0 = (vb & 3) * 256;
        int b = bh >> 3, h = bh & 7;
        const float4* vg = (const float4*)vin;
#pragma unroll
        for (int j = 0; j < 16; j++) {
            int i = tid + j * 256;
            int s = i >> 4, d4 = i & 15;
            float4 xv = vg[((size_t)((b * 1024 + sc0 + s) * 8 + h)) * 16 + d4];
            const float* px = &xv.x;
#pragma unroll
            for (int jj = 0; jj < 4; jj++)
                smH[(d4 * 4 + jj) * 264 + s] = __float2half_rn(px[jj]);
        }
        __syncthreads();
        u64* dst = g_vV + (size_t)bh * 32768;
#pragma unroll
        for (int j = 0; j < 8; j++) {
            int i = tid + j * 256;            // 0..2047
            int c = i >> 7;                   // local chunk 0..15
            int jj = (i >> 5) & 3;            // pair index
            int d0 = (i & 31) * 2;            // d, d+1
            int spA = c * 8 + jj, spB = spA + 4;   // local spairs
            u64 vv[2];
#pragma unroll
            for (int t = 0; t < 2; t++) {
                int d = d0 + t;
                uint32_t lo = (uint32_t)__half_as_ushort(smH[d * 264 + 2 * spA])
                            | ((uint32_t)__half_as_ushort(smH[d * 264 + 2 * spA + 1]) << 16);
                uint32_t hi = (uint32_t)__half_as_ushort(smH[d * 264 + 2 * spB])
                            | ((uint32_t)__half_as_ushort(smH[d * 264 + 2 * spB + 1]) << 16);
                vv[t] = (u64)lo | ((u64)hi << 32);
            }
            size_t base = ((size_t)((sc0 >> 4) + c) * 4 + jj) * 64 + d0;
            *(ulonglong2*)&dst[base] = make_ulonglong2(vv[0], vv[1]);
        }
        return;
    }

    const int isK = (bid >= 256);
    const float* x = isK ? kin : qin;
    const float* w = isK ? wk : wq;
    const float* bias = isK ? bk : bq;
    if (tid < NQV * 64) sw[tid] = w[tid];
    if (tid < NQV) sb[tid] = bias[tid];
    __syncthreads();

    int n  = (bid & 255) * 256 + tid;
    int bh = n >> 10, loc = n & 1023;
    int b = bh >> 3, h = bh & 7;
    const float* xr = x + (size_t)((b * 1024 + loc) * HHN + h) * 64;

    float th[NQV];
#pragma unroll
    for (int j = 0; j < NQV; j++) th[j] = sb[j];
#pragma unroll 4
    for (int d = 0; d < 64; d += 4) {
        float4 xv = *(const float4*)(xr + d);
#pragma unroll
        for (int j = 0; j < NQV; j++) {
            th[j] += xv.x * sw[j * 64 + d]     + xv.y * sw[j * 64 + d + 1]
                   + xv.z * sw[j * 64 + d + 2] + xv.w * sw[j * 64 + d + 3];
        }
    }
#pragma unroll
    for (int j = 0; j < NQV; j++) th[j] = tanhf(th[j]) * PI_F;
    float bt[3];
#pragma unroll
    for (int p = 0; p < 3; p++) bt[p] = th[p] * th[p + 1];

    float co[16], si[16];
#pragma unroll
    for (int d = 0; d < 16; d++) {
        float a = 0.f;
        a += ((d >> 3) & 1) ? -th[0] : th[0];
        a += ((d >> 2) & 1) ? -th[1] : th[1];
        a += ((d >> 1) & 1) ? -th[2] : th[2];
        a += ( d       & 1) ? -th[3] : th[3];
        a += (((d >> 3) ^ (d >> 2)) & 1) ? -bt[0] : bt[0];
        a += (((d >> 2) ^ (d >> 1)) & 1) ? -bt[1] : bt[1];
        a += (((d >> 1) ^  d      ) & 1) ? -bt[2] : bt[2];
        sincosf(-0.5f * a, &si[d], &co[d]);
    }
    float re[16], im[16];
#pragma unroll
    for (int d = 0; d < 16; d++) { re[d] = co[d]; im[d] = si[d]; }
#pragma unroll
    for (int hs = 1; hs < 16; hs <<= 1) {
#pragma unroll
        for (int i = 0; i < 16; i++) {
            if ((i & hs) == 0) {
                int j2 = i | hs;
                float ar = re[i], ai = im[i], br = re[j2], bi = im[j2];
                re[i] = ar + br;  im[i] = ai + bi;
                re[j2] = ar - br; im[j2] = ai - bi;
            }
        }
    }

    // Q scaled x128 (0.0625*128 = 8) -> p' = (128 fid)^2
    const float sc = isK ? 0.0625f : 8.0f;
    float fr[16], fi[16];
#pragma unroll
    for (int d = 0; d < 16; d++) {
        float tr = re[d] * sc, ti = im[d] * sc;
        fr[d] = tr * co[d] - ti * si[d];
        fi[d] = tr * si[d] + ti * co[d];
    }

    uint32_t uw[40];   // [qr_h 0..7][qi_h 8..15][qr_l 24..31][qi_l 32..39]
#pragma unroll
    for (int j = 0; j < 8; j++) {
        uint32_t hp;
        hp = bfpack(fr[2*j], fr[2*j+1]);
        uw[j] = hp;
        uw[24 + j] = bfpack(fr[2*j] - bflowf(hp), fr[2*j+1] - bfhighf(hp));
        hp = bfpack(fi[2*j], fi[2*j+1]);
        uw[8 + j] = hp;
        uw[32 + j] = bfpack(fi[2*j] - bflowf(hp), fi[2*j+1] - bfhighf(hp));
    }
    if (!isK) {
        uint32_t o[48];
#pragma unroll
        for (int j = 0; j < 8; j++) {
            o[j]      = uw[j];
            o[8 + j]  = uw[8 + j];
            o[16 + j] = uw[j] ^ 0x80008000u;
            o[24 + j] = uw[24 + j];
            o[32 + j] = uw[32 + j];
            o[40 + j] = uw[24 + j] ^ 0x80008000u;
        }
        uint4* o4 = (uint4*)(g_qA + (size_t)n * 96);
#pragma unroll
        for (int q = 0; q < 12; q++)
            o4[q] = make_uint4(o[4*q], o[4*q+1], o[4*q+2], o[4*q+3]);
    } else {
        ulonglong2* o2 = (ulonglong2*)(g_kBi + (size_t)n * 16);
#pragma unroll
        for (int j = 0; j < 8; j++)
            o2[j] = make_ulonglong2((u64)uw[2*j]   | ((u64)uw[24 + 2*j]   << 32),
                                    (u64)uw[2*j+1] | ((u64)uw[24 + 2*j+1] << 32));
    }
}

// ======================================================================
// Fused attention: direct 4-gemm scores, fp16 context, occupancy 4.
// smem: scores 33536 B + 8 x 2560 B warp buffers = 54016 B (216 KB @ occ 4)
// ======================================================================
#define SC_STRIDE 524
#define SC_BYTES (16 * SC_STRIDE * 4)       // 33536
#define WBUF_BYTES 2560                      // 2 K stages (1280) / 2 V stages (1152)
#define SMEM_BYTES (SC_BYTES + 8 * WBUF_BYTES)   // 54016

__global__ void __launch_bounds__(256, 4) attn_fused(float* __restrict__ out)
{
    extern __shared__ uint32_t smb[];
    uint32_t* sc32 = smb;                    // [16][524] fp16x2 score pairs
    __shared__ float sred[8][16];
    __shared__ float sinv[16];

    const int bh = blockIdx.y;
    const int l0 = blockIdx.x * 16;
    const int b = bh >> 3, h = bh & 7;
    const int tid = threadIdx.x;
    const int w = tid >> 5, lane = tid & 31;
    const int gr = lane >> 2, ctg = lane & 3;

    char* wbufb = (char*)smb + SC_BYTES + w * WBUF_BYTES;
    const uint32_t wsa = s2u(wbufb);

    // resident bf16 Q fragments: g = {qr, qi, nqr}, hi+lo
    uint32_t Ah[3][4], Al[3][4];
    {
        const uint32_t* qa = (const uint32_t*)g_qA + (size_t)bh * 49152 + (size_t)l0 * 48;
#pragma unroll
        for (int g = 0; g < 3; g++) {
            Ah[g][0] = qa[gr * 48 + g * 8 + ctg];
            Ah[g][1] = qa[(gr + 8) * 48 + g * 8 + ctg];
            Ah[g][2] = qa[gr * 48 + g * 8 + 4 + ctg];
            Ah[g][3] = qa[(gr + 8) * 48 + g * 8 + 4 + ctg];
            Al[g][0] = qa[gr * 48 + 24 + g * 8 + ctg];
            Al[g][1] = qa[(gr + 8) * 48 + 24 + g * 8 + ctg];
            Al[g][2] = qa[gr * 48 + 24 + g * 8 + 4 + ctg];
            Al[g][3] = qa[(gr + 8) * 48 + 24 + g * 8 + 4 + ctg];
        }
    }

    // ---- phase A staging addresses ----
    const u64* kg = g_kBi + (size_t)bh * 16384;
    const int kr_ = lane >> 2, kq = lane & 3;
    const uint32_t kd0 = wsa + (uint32_t)(kr_ * 20 + kq * 2) * 8;
    const uint32_t kd1 = kd0 + 64;                      // +8 u64
    const u64* ks0 = kg + (w * 8 + kr_) * 16 + kq * 2;
    const u64* ks1 = ks0 + 8;

    auto issueK = [&](int c) {
        const uint32_t so = (c & 1) ? 1280u : 0u;
        const size_t go = (size_t)c * 1024;
        cpa16s(kd0 + so, ks0 + go);
        cpa16s(kd1 + so, ks1 + go);
        cpa_commit();
    };

    uint32_t* srow0 = sc32 + gr * SC_STRIDE + w * 4 + ctg;
    uint32_t* srow1 = srow0 + 8 * SC_STRIDE;

    float rs0 = 0.f, rs1 = 0.f;
    issueK(0);
    issueK(1);

#pragma unroll 1
    for (int c = 0; c < 16; c++) {
        if (c < 15) cpa_wait<1>(); else cpa_wait<0>();
        __syncwarp();
        const u64* bb = (const u64*)(wbufb + ((c & 1) ? 1280 : 0)) + gr * 20;

        u64 Br0 = bb[ctg];
        u64 Br1 = bb[4 + ctg];
        u64 Bi0 = bb[8 + ctg];
        u64 Bi1 = bb[12 + ctg];
        __syncwarp();
        if (c < 14) issueK(c + 2);

        uint32_t krh0 = (uint32_t)Br0, krh1 = (uint32_t)Br1;
        uint32_t krl0 = (uint32_t)(Br0 >> 32), krl1 = (uint32_t)(Br1 >> 32);
        uint32_t kih0 = (uint32_t)Bi0, kih1 = (uint32_t)Bi1;
        uint32_t kil0 = (uint32_t)(Bi0 >> 32), kil1 = (uint32_t)(Bi1 >> 32);

        float4 fr4 = make_float4(0.f, 0.f, 0.f, 0.f);
        float4 fi4 = make_float4(0.f, 0.f, 0.f, 0.f);
        mma_bf16(fr4, Ah[0], krh0, krh1);
        mma_bf16(fi4, Ah[1], krh0, krh1);
        mma_bf16(fr4, Ah[0], krl0, krl1);
        mma_bf16(fi4, Ah[1], krl0, krl1);
        mma_bf16(fr4, Al[0], krh0, krh1);
        mma_bf16(fi4, Al[1], krh0, krh1);
        mma_bf16(fr4, Ah[1], kih0, kih1);
        mma_bf16(fi4, Ah[2], kih0, kih1);
        mma_bf16(fr4, Ah[1], kil0, kil1);
        mma_bf16(fi4, Ah[2], kil0, kil1);
        mma_bf16(fr4, Al[1], kih0, kih1);
        mma_bf16(fi4, Al[2], kih0, kih1);

        float p0 = fr4.x * fr4.x + fi4.x * fi4.x;
        float p1 = fr4.y * fr4.y + fi4.y * fi4.y;
        float p2 = fr4.z * fr4.z + fi4.z * fi4.z;
        float p3 = fr4.w * fr4.w + fi4.w * fi4.w;

        srow0[c * 32] = hfpack(p0, p1);
        srow1[c * 32] = hfpack(p2, p3);
        rs0 += p0 + p1; rs1 += p2 + p3;
    }

    // ---- rowsums ----
    rs0 += __shfl_xor_sync(0xFFFFFFFFu, rs0, 1);
    rs0 += __shfl_xor_sync(0xFFFFFFFFu, rs0, 2);
    rs1 += __shfl_xor_sync(0xFFFFFFFFu, rs1, 1);
    rs1 += __shfl_xor_sync(0xFFFFFFFFu, rs1, 2);
    if (ctg == 0) { sred[w][gr] = rs0; sred[w][gr + 8] = rs1; }
    __syncthreads();

    // ---- phase C mapping: warp = (dq d-half, sh s-quarter) ----
    const int dq = w >> 2, sh = w & 3;
    const u64* vG = g_vV + (size_t)bh * 32768 + (size_t)(sh * 16) * 256 + dq * 32;
    const int vj = lane >> 3, vd8 = lane & 7;
    const uint32_t vdst0 = wsa + (uint32_t)(vj * 36 + vd8 * 2) * 8;
    const uint32_t vdst1 = vdst0 + 128;                 // +16 u64
    const u64* vsrc0 = vG + vj * 64 + vd8 * 2;
    const u64* vsrc1 = vsrc0 + 16;

    auto issueV = [&](int c) {
        const uint32_t vso = (c & 1) ? 1152u : 0u;
        const size_t go = (size_t)c * 256;
        cpa16s(vdst0 + vso, vsrc0 + go);
        cpa16s(vdst1 + vso, vsrc1 + go);
        cpa_commit();
    };
    issueV(0);
    issueV(1);

    if (tid < 16) {
        float s = 0.f;
#pragma unroll
        for (int ww = 0; ww < 8; ww++) s += sred[ww][tid];
        sinv[tid] = 1.0f / (s + 0.016384f);
    }
    __syncthreads();

    // ---- phase B: single normalized weights pass ----
    {
        float4* wout = (float4*)(out + (size_t)CTX_ELEMS + ((size_t)bh * 1024 + l0) * 1024);
#pragma unroll 4
        for (int i = tid; i < 4096; i += 256) {
            int row = i >> 8, pq = i & 255;
            uint2 v = *(const uint2*)&sc32[row * SC_STRIDE + pq * 2];
            float2 f0 = __half22float2(*(const half2*)&v.x);
            float2 f1 = __half22float2(*(const half2*)&v.y);
            float iv = sinv[row];
            wout[(size_t)row * 256 + pq] =
                make_float4(f0.x * iv, f0.y * iv, f1.x * iv, f1.y * iv);
        }
    }

    // ---- phase C main loop: 16 chunks of 8 spairs ----
    float4 cac[4];
#pragma unroll
    for (int nt = 0; nt < 4; nt++) cac[nt] = make_float4(0.f, 0.f, 0.f, 0.f);

    const uint32_t* sr0 = sc32 + gr * SC_STRIDE + sh * 128 + ctg;
    const uint32_t* sr1 = sr0 + 8 * SC_STRIDE;

#pragma unroll 1
    for (int c = 0; c < 16; c++) {
        if (c < 15) cpa_wait<1>(); else cpa_wait<0>();
        __syncwarp();
        const u64* vb = (const u64*)(wbufb + ((c & 1) ? 1152 : 0)) + ctg * 36;

        u64 bv[4];
#pragma unroll
        for (int nt = 0; nt < 4; nt++) bv[nt] = vb[nt * 8 + gr];
        uint32_t aH[4];
        aH[0] = sr0[c * 8];
        aH[1] = sr1[c * 8];
        aH[2] = sr0[c * 8 + 4];
        aH[3] = sr1[c * 8 + 4];
        __syncwarp();
        if (c < 14) issueV(c + 2);

#pragma unroll
        for (int nt = 0; nt < 4; nt++)
            mma_f16(cac[nt], aH, (uint32_t)bv[nt], (uint32_t)(bv[nt] >> 32));
    }

    // ---- 4-way cross-s-quarter reduction (reuse warp-buffer smem) ----
    __syncthreads();
    float* pf = (float*)((char*)smb + SC_BYTES);   // [8 warps][16 l][stride 40]
    {
        float* pw = pf + w * 640;
#pragma unroll
        for (int nt = 0; nt < 4; nt++) {
            *(float2*)(pw + gr * 40 + nt * 8 + 2 * ctg) = make_float2(cac[nt].x, cac[nt].y);
            *(float2*)(pw + (gr + 8) * 40 + nt * 8 + 2 * ctg) = make_float2(cac[nt].z, cac[nt].w);
        }
    }
    __syncthreads();
    {
        int l = tid >> 4, dqd = tid & 15;
        int wb = (dqd >= 8) ? 4 : 0;
        int col = (dqd & 7) * 4;
        float4 sum = make_float4(0.f, 0.f, 0.f, 0.f);
#pragma unroll
        for (int s = 0; s < 4; s++) {
            float4 v = *(const float4*)(pf + (wb + s) * 640 + l * 40 + col);
            sum.x += v.x; sum.y += v.y; sum.z += v.z; sum.w += v.w;
        }
        float iv = sinv[l];
        sum.x *= iv; sum.y *= iv; sum.z *= iv; sum.w *= iv;
        *(float4*)&out[((size_t)((b * 1024 + l0 + l) * 8 + h)) * 64 + dqd * 4] = sum;
    }
}

// ======================================================================
extern "C" void kernel_launch(void* const* d_in, const int* in_sizes, int n_in,
                              void* d_out, int out_size)
{
    (void)in_sizes; (void)n_in; (void)out_size;
    const float* q  = (const float*)d_in[0];
    const float* k  = (const float*)d_in[1];
    const float* v  = (const float*)d_in[2];
    const float* wq = (const float*)d_in[3];
    const float* bq = (const float*)d_in[4];
    const float* wk = (const float*)d_in[5];
    const float* bk = (const float*)d_in[6];
    float* out = (float*)d_out;

    cudaFuncSetAttribute(prep_kernel, cudaFuncAttributeMaxDynamicSharedMemorySize, PREP_SMEM);
    cudaFuncSetAttribute(attn_fused,  cudaFuncAttributeMaxDynamicSharedMemorySize, SMEM_BYTES);

    prep_kernel<<<768, 256, PREP_SMEM>>>(q, k, v, wq, bq, wk, bk);
    attn_fused<<<dim3(64, BHN), 256, SMEM_BYTES>>>(out);
}